// round 1
// baseline (speedup 1.0000x reference)
#include <cuda_runtime.h>

// dense_image_warp: out[b,y,x,c] = bilinear(image[b], y - flow[b,y,x,0], x - flow[b,y,x,1])
// B=8, H=512, W=512, C=16, fp32. Shapes hardcoded per setup_inputs.

#define Hh 512
#define Ww 512
#define Cc 16

__global__ __launch_bounds__(256) void warp_kernel(
    const float4* __restrict__ img4,   // image as float4 (4 channels per elt)
    const float2* __restrict__ flow2,  // flow as float2 per pixel
    float4* __restrict__ out4,
    int n_threads)
{
    int t = blockIdx.x * blockDim.x + threadIdx.x;
    if (t >= n_threads) return;

    int p  = t >> 2;      // pixel index: ((b*H + y)*W + x)
    int cg = t & 3;       // channel group (4 floats each)

    int x = p & (Ww - 1);
    int y = (p >> 9) & (Hh - 1);
    int b = p >> 18;

    float2 f = __ldg(&flow2[p]);
    float qy = (float)y - f.x;
    float qx = (float)x - f.y;

    float fy = fminf(fmaxf(floorf(qy), 0.0f), (float)(Hh - 2));
    float fx = fminf(fmaxf(floorf(qx), 0.0f), (float)(Ww - 2));
    float ay = fminf(fmaxf(qy - fy, 0.0f), 1.0f);
    float ax = fminf(fmaxf(qx - fx, 0.0f), 1.0f);
    int iy = (int)fy;
    int ix = (int)fx;

    // float4 index of top-left neighbor for this channel group
    int base = (((b << 9) + iy) << 9) + ix;   // pixel index of TL in image
    int i_tl = (base << 2) + cg;
    int i_tr = i_tl + 4;            // ix+1
    int i_bl = i_tl + (Ww << 2);    // iy+1
    int i_br = i_bl + 4;

    float4 tl = __ldg(&img4[i_tl]);
    float4 tr = __ldg(&img4[i_tr]);
    float4 bl = __ldg(&img4[i_bl]);
    float4 br = __ldg(&img4[i_br]);

    float4 top, bot, r;
    top.x = fmaf(ax, tr.x - tl.x, tl.x);
    top.y = fmaf(ax, tr.y - tl.y, tl.y);
    top.z = fmaf(ax, tr.z - tl.z, tl.z);
    top.w = fmaf(ax, tr.w - tl.w, tl.w);
    bot.x = fmaf(ax, br.x - bl.x, bl.x);
    bot.y = fmaf(ax, br.y - bl.y, bl.y);
    bot.z = fmaf(ax, br.z - bl.z, bl.z);
    bot.w = fmaf(ax, br.w - bl.w, bl.w);
    r.x = fmaf(ay, bot.x - top.x, top.x);
    r.y = fmaf(ay, bot.y - top.y, top.y);
    r.z = fmaf(ay, bot.z - top.z, top.z);
    r.w = fmaf(ay, bot.w - top.w, top.w);

    out4[t] = r;
}

extern "C" void kernel_launch(void* const* d_in, const int* in_sizes, int n_in,
                              void* d_out, int out_size)
{
    const float4* img4  = (const float4*)d_in[0];
    const float2* flow2 = (const float2*)d_in[1];
    float4* out4 = (float4*)d_out;

    int n_threads = out_size / 4;          // 8*512*512*16 / 4 = 8,388,608
    int block = 256;
    int grid = (n_threads + block - 1) / block;
    warp_kernel<<<grid, block>>>(img4, flow2, out4, n_threads);
}